// round 7
// baseline (speedup 1.0000x reference)
#include <cuda_runtime.h>

static constexpr int Bn   = 128;
static constexpr int Nn   = 256;
static constexpr int SMAX = 300;

__device__ float    g_partials[Bn];   // per-batch (pair + setsize) loss
__device__ unsigned g_count = 0;

__device__ __forceinline__ float fsqrt_ap(float x) {
    float r;
    asm("sqrt.approx.f32 %0, %1;" : "=f"(r) : "f"(x));
    return r;
}

// Warp-wide min for non-negative floats (u32 bit ordering == float ordering;
// NaN bit patterns are huge, so they lose the min — desired).
__device__ __forceinline__ float warp_min_nonneg(float x) {
    unsigned u = __float_as_uint(x), r;
    asm("redux.sync.min.u32 %0, %1, 0xffffffff;" : "=r"(r) : "r"(u));
    return __uint_as_float(r);
}

// ---------------------------------------------------------------------------
// One block per batch (grid=128, 1024 threads). Warp-specialized:
//   warps  0-15 (t <  512): pair loss (2 rows/lane, 4 row-groups x 4 j-quarters)
//   warps 16-25 (t in [512,812)): setsize column sums, 32-deep MLP streaming
//   warps 26-31: barriers only
// Setsize DRAM latency hides under pair compute on the same SM; 8 warps/SMSP
// cover the pair loop's LDS/MUFU latency chains. Last block reduces partials.
// ---------------------------------------------------------------------------
__global__ void __launch_bounds__(1024, 1) fused_kernel(
    const int*   __restrict__ pcls,  const int*   __restrict__ pchg,
    const int*   __restrict__ n_part,
    const float* __restrict__ cl_logits, const float* __restrict__ ch_logits,
    const float* __restrict__ ppos,  const float* __restrict__ fpos,
    const float* __restrict__ pmom,  const float* __restrict__ fmom,
    const float* __restrict__ pe,    const float* __restrict__ fe,
    const float* __restrict__ pred,
    float* __restrict__ out)
{
    __shared__ float  s_csum[Nn * 15];   // nllc[c] + nllq[q] + fe^2 per (j, cc)
    __shared__ float  s_fe[Nn];          // fe_j
    __shared__ float4 s_fa[Nn];          // fx, fy, fz, |fpos|^2
    __shared__ float4 s_fb[Nn];          // fmx, fmy, fmz, |fmom|^2
    __shared__ float  s_colmin[4][Nn];   // per row-group column mins
    __shared__ float  s_rq[4][Nn];       // per j-quarter row mins
    __shared__ float  s_x[SMAX];         // setsize column means
    __shared__ float  s_pred8[8];
    __shared__ float  s_redm[16];
    __shared__ float  s_rede[16];
    __shared__ unsigned s_islast;

    const int t    = threadIdx.x;
    const int b    = blockIdx.x;
    const int w    = t >> 5;
    const int lane = t & 31;

    const bool is_pair = (t < 512);
    const bool is_set  = (t >= 512) && (t < 512 + SMAX);

    // ================= PROLOGUE =================
    float v[32];
    const float* sp = nullptr;
    if (is_set) {
        // prefetch setsize chunk 0 (overlaps the table prologue)
        sp = pred + (size_t)b * Nn * SMAX + (t - 512);
        #pragma unroll
        for (int k = 0; k < 32; k++) v[k] = sp[(size_t)k * SMAX];
    }

    if (t < Nn) {
        const int j  = t;
        const int gj = b * Nn + j;
        float nc[5], nq[3];
        {
            const float* cl = cl_logits + gj * 5;
            float x0 = cl[0], x1 = cl[1], x2 = cl[2], x3 = cl[3], x4 = cl[4];
            float m  = fmaxf(fmaxf(fmaxf(x0, x1), fmaxf(x2, x3)), x4);
            float s  = __expf(x0 - m) + __expf(x1 - m) + __expf(x2 - m)
                     + __expf(x3 - m) + __expf(x4 - m);
            float lse = m + __logf(s);
            nc[0] = lse - x0; nc[1] = lse - x1; nc[2] = lse - x2;
            nc[3] = lse - x3; nc[4] = lse - x4;
        }
        {
            const float* ch = ch_logits + gj * 3;
            float x0 = ch[0], x1 = ch[1], x2 = ch[2];
            float m  = fmaxf(fmaxf(x0, x1), x2);
            float s  = __expf(x0 - m) + __expf(x1 - m) + __expf(x2 - m);
            float lse = m + __logf(s);
            nq[0] = lse - x0; nq[1] = lse - x1; nq[2] = lse - x2;
        }
        float fx = fpos[gj * 3 + 0], fy = fpos[gj * 3 + 1], fz = fpos[gj * 3 + 2];
        float mx = fmom[gj * 3 + 0], my = fmom[gj * 3 + 1], mz = fmom[gj * 3 + 2];
        float fev = fe[gj];
        float np  = fmaf(fx, fx, fmaf(fy, fy, fz * fz));
        float nm  = fmaf(mx, mx, fmaf(my, my, mz * mz));
        float fe2 = fev * fev;
        s_fa[j] = make_float4(fx, fy, fz, np);
        s_fb[j] = make_float4(mx, my, mz, nm);
        s_fe[j] = fev;
        #pragma unroll
        for (int c = 0; c < 5; c++)
            #pragma unroll
            for (int q = 0; q < 3; q++)
                s_csum[j * 15 + c * 3 + q] = nc[c] + nq[q] + fe2;
    }

    // pair-side row constants
    int   cc0 = 0, cc1 = 0;
    float rp0=0, rm0=0, pe20=0, m2x0=0, m2y0=0, m2z0=0, n2x0=0, n2y0=0, n2z0=0, m2e0=0;
    float rp1=0, rm1=0, pe21=0, m2x1=0, m2y1=0, m2z1=0, n2x1=0, n2y1=0, n2z1=0, m2e1=0;
    int r = 0, q = 0, i0 = 0, i1 = 0;
    if (is_pair) {
        r  = w & 3;            // row-group: rows [r*64, r*64+64)
        q  = w >> 2;           // j-quarter: cols [q*64, q*64+64)
        i0 = r * 64 + lane;
        i1 = i0 + 32;
        const int gi0 = b * Nn + i0;
        const int gi1 = b * Nn + i1;

        cc0 = pcls[gi0] * 3 + pchg[gi0];
        cc1 = pcls[gi1] * 3 + pchg[gi1];

        float px0 = ppos[gi0*3+0], py0 = ppos[gi0*3+1], pz0 = ppos[gi0*3+2];
        float qx0 = pmom[gi0*3+0], qy0 = pmom[gi0*3+1], qz0 = pmom[gi0*3+2];
        float pe0v = pe[gi0];
        float px1 = ppos[gi1*3+0], py1 = ppos[gi1*3+1], pz1 = ppos[gi1*3+2];
        float qx1 = pmom[gi1*3+0], qy1 = pmom[gi1*3+1], qz1 = pmom[gi1*3+2];
        float pe1v = pe[gi1];

        rp0 = fmaf(px0, px0, fmaf(py0, py0, pz0 * pz0));
        rm0 = fmaf(qx0, qx0, fmaf(qy0, qy0, qz0 * qz0));
        pe20 = pe0v * pe0v;
        m2x0 = -2.f*px0; m2y0 = -2.f*py0; m2z0 = -2.f*pz0;
        n2x0 = -2.f*qx0; n2y0 = -2.f*qy0; n2z0 = -2.f*qz0;
        m2e0 = -2.f*pe0v;
        rp1 = fmaf(px1, px1, fmaf(py1, py1, pz1 * pz1));
        rm1 = fmaf(qx1, qx1, fmaf(qy1, qy1, qz1 * qz1));
        pe21 = pe1v * pe1v;
        m2x1 = -2.f*px1; m2y1 = -2.f*py1; m2z1 = -2.f*pz1;
        n2x1 = -2.f*qx1; n2y1 = -2.f*qy1; n2z1 = -2.f*qz1;
        m2e1 = -2.f*pe1v;
    }

    __syncthreads();

    // ================= MAIN PHASE (no internal barriers) =================
    if (is_pair) {
        float rowmin0 = 1e30f, rowmin1 = 1e30f;
        const int jend = q * 64 + 64;
        #pragma unroll 4
        for (int j = q * 64; j < jend; j++) {
            float4 a  = s_fa[j];
            float4 bb = s_fb[j];
            float fej = s_fe[j];
            float cs0 = s_csum[j * 15 + cc0];
            float cs1 = s_csum[j * 15 + cc1];

            float d2p0 = rp0 + a.w;
            d2p0 = fmaf(m2x0, a.x, d2p0);
            d2p0 = fmaf(m2y0, a.y, d2p0);
            d2p0 = fmaf(m2z0, a.z, d2p0);
            float d2m0 = rm0 + bb.w;
            d2m0 = fmaf(n2x0, bb.x, d2m0);
            d2m0 = fmaf(n2y0, bb.y, d2m0);
            d2m0 = fmaf(n2z0, bb.z, d2m0);
            float l0 = fmaf(m2e0, fej, cs0) + pe20;
            l0 += fsqrt_ap(d2p0) + fsqrt_ap(d2m0);
            rowmin0 = fminf(rowmin0, l0);

            float d2p1 = rp1 + a.w;
            d2p1 = fmaf(m2x1, a.x, d2p1);
            d2p1 = fmaf(m2y1, a.y, d2p1);
            d2p1 = fmaf(m2z1, a.z, d2p1);
            float d2m1 = rm1 + bb.w;
            d2m1 = fmaf(n2x1, bb.x, d2m1);
            d2m1 = fmaf(n2y1, bb.y, d2m1);
            d2m1 = fmaf(n2z1, bb.z, d2m1);
            float l1 = fmaf(m2e1, fej, cs1) + pe21;
            l1 += fsqrt_ap(d2p1) + fsqrt_ap(d2m1);
            rowmin1 = fminf(rowmin1, l1);

            float cm = warp_min_nonneg(fminf(l0, l1));
            if (lane == 0) s_colmin[r][j] = cm;
        }
        s_rq[q][i0] = rowmin0;
        s_rq[q][i1] = rowmin1;
    } else if (is_set) {
        float acc0 = 0.f, acc1 = 0.f, acc2 = 0.f, acc3 = 0.f;
        for (int c = 0; c < 8; c++) {
            #pragma unroll
            for (int k = 0; k < 32; k += 4) {
                acc0 += v[k + 0];
                acc1 += v[k + 1];
                acc2 += v[k + 2];
                acc3 += v[k + 3];
            }
            if (c < 7) {
                sp += (size_t)32 * SMAX;
                #pragma unroll
                for (int k = 0; k < 32; k++) v[k] = sp[(size_t)k * SMAX];
            }
        }
        s_x[t - 512] = ((acc0 + acc1) + (acc2 + acc3)) * (1.f / Nn);
    }

    __syncthreads();

    // ================= EPILOGUE (warps 0-9 do all reductions) =================
    // pair combine: sum over rows of rowmin + sum over cols of colmin
    if (t < Nn) {
        float rm = fminf(fminf(s_rq[0][t], s_rq[1][t]),
                         fminf(s_rq[2][t], s_rq[3][t]));
        float cm = fminf(fminf(s_colmin[0][t], s_colmin[1][t]),
                         fminf(s_colmin[2][t], s_colmin[3][t]));
        float pv = rm + cm;
        #pragma unroll
        for (int o = 16; o; o >>= 1) pv += __shfl_xor_sync(0xffffffffu, pv, o);
        if (lane == 0) s_pred8[w] = pv;
    }
    // setsize max (warps 0-9 cover t<320; inactive cols use -inf)
    if (t < 320) {
        float sv = (t < SMAX) ? s_x[t] : -1e30f;
        #pragma unroll
        for (int o = 16; o; o >>= 1) sv = fmaxf(sv, __shfl_xor_sync(0xffffffffu, sv, o));
        if (lane == 0) s_redm[w] = sv;
    }
    __syncthreads();
    if (t < 320) {
        float m = s_redm[0];
        #pragma unroll
        for (int wv = 1; wv < 10; wv++) m = fmaxf(m, s_redm[wv]);
        float e = (t < SMAX) ? __expf(s_x[t] - m) : 0.f;
        #pragma unroll
        for (int o = 16; o; o >>= 1) e += __shfl_xor_sync(0xffffffffu, e, o);
        if (lane == 0) s_rede[w] = e;
    }
    __syncthreads();
    if (t == 0) {
        float pair = 0.f;
        #pragma unroll
        for (int wv = 0; wv < 8; wv++) pair += s_pred8[wv];
        float m = s_redm[0];
        #pragma unroll
        for (int wv = 1; wv < 10; wv++) m = fmaxf(m, s_redm[wv]);
        float Z = 0.f;
        #pragma unroll
        for (int wv = 0; wv < 10; wv++) Z += s_rede[wv];
        float logZ = m + __logf(Z);
        g_partials[b] = pair + (logZ - s_x[n_part[b]]);
    }

    // ================= COMPLETION-COUNTER FINAL REDUCTION =================
    if (t == 0) {
        __threadfence();
        unsigned old = atomicAdd(&g_count, 1u);
        s_islast = (old == (unsigned)Bn - 1u) ? 1u : 0u;
    }
    __syncthreads();
    if (s_islast) {
        if (t < Bn) {
            float pv = ((volatile float*)g_partials)[t];
            #pragma unroll
            for (int o = 16; o; o >>= 1) pv += __shfl_xor_sync(0xffffffffu, pv, o);
            if (lane == 0) s_redm[w] = pv;
        }
        __syncthreads();
        if (t == 0) {
            float s = 0.f;
            #pragma unroll
            for (int wv = 0; wv < 4; wv++) s += s_redm[wv];
            out[0] = s * (1.0f / Bn);
            g_count = 0;   // reset for next graph replay
        }
    }
}

extern "C" void kernel_launch(void* const* d_in, const int* in_sizes, int n_in,
                              void* d_out, int out_size)
{
    const int*   pcls  = (const int*)  d_in[0];
    const int*   pchg  = (const int*)  d_in[1];
    const int*   npart = (const int*)  d_in[2];
    const float* cl    = (const float*)d_in[3];
    const float* ch    = (const float*)d_in[4];
    const float* ppos  = (const float*)d_in[5];
    const float* fpos  = (const float*)d_in[6];
    const float* pmom  = (const float*)d_in[7];
    const float* fmom  = (const float*)d_in[8];
    const float* pe    = (const float*)d_in[9];
    const float* fe    = (const float*)d_in[10];
    const float* pred  = (const float*)d_in[11];

    fused_kernel<<<Bn, 1024>>>(pcls, pchg, npart, cl, ch,
                               ppos, fpos, pmom, fmom, pe, fe, pred,
                               (float*)d_out);
}

// round 8
// speedup vs baseline: 1.1345x; 1.1345x over previous
#include <cuda_runtime.h>

static constexpr int Bn   = 128;
static constexpr int Nn   = 256;
static constexpr int SMAX = 300;

typedef unsigned long long u64;

__device__ float    g_partials[2 * Bn];  // [0..Bn) pair, [Bn..2Bn) setsize
__device__ unsigned g_count = 0;

__device__ __forceinline__ float fsqrt_ap(float x) {
    float r;
    asm("sqrt.approx.f32 %0, %1;" : "=f"(r) : "f"(x));
    return r;
}
// Warp-wide min for non-negative floats (u32 ordering == float ordering;
// NaN bit patterns are huge, so they lose the min — desired).
__device__ __forceinline__ float warp_min_nonneg(float x) {
    unsigned u = __float_as_uint(x), r;
    asm("redux.sync.min.u32 %0, %1, 0xffffffff;" : "=r"(r) : "r"(u));
    return __uint_as_float(r);
}
// ---- f32x2 packed helpers (Blackwell) ----
__device__ __forceinline__ u64 pack2(float lo, float hi) {
    u64 d;
    asm("mov.b64 %0, {%1, %2};" : "=l"(d) : "f"(lo), "f"(hi));
    return d;
}
__device__ __forceinline__ void unpack2(float& lo, float& hi, u64 v) {
    asm("mov.b64 {%0, %1}, %2;" : "=f"(lo), "=f"(hi) : "l"(v));
}
__device__ __forceinline__ u64 dup2(float x) {
    return pack2(x, x);
}
__device__ __forceinline__ u64 fma2(u64 a, u64 b, u64 c) {
    u64 d;
    asm("fma.rn.f32x2 %0, %1, %2, %3;" : "=l"(d) : "l"(a), "l"(b), "l"(c));
    return d;
}
__device__ __forceinline__ u64 add2(u64 a, u64 b) {
    u64 d;
    asm("add.rn.f32x2 %0, %1, %2;" : "=l"(d) : "l"(a), "l"(b));
    return d;
}

struct PairSmem {
    u64   geo[Nn * 10];     // per j (80B): fx2,fy2,fz2,np2, mx2,my2,mz2,nm2, fe2, pad
    float csum[Nn * 15];    // nllc[c]+nllq[q]+fe^2 per (j, cls*3+chg)
    float colmin[4][Nn];    // per row-group column mins
    float rq[4][Nn];        // per j-quarter row mins
    float red[16];
};
struct SetSmem { float x[SMAX]; float red[16]; };
union FusedSmem { PairSmem p; SetSmem s; };

// ---------------------------------------------------------------------------
// grid = 256 x 512 threads. blocks [0,128): pair loss; [128,256): setsize.
// LUT placement gives 108 mixed pair+set SMs, no SM with two pair blocks.
// Pair block: 16 warps = 4 row-groups x 4 j-quarters, 2 rows/lane packed into
// f32x2 registers; geo tables stored pre-duplicated so broadcast LDS.128
// yields ready-packed operands. Last block reduces all partials.
// ---------------------------------------------------------------------------
__global__ void __launch_bounds__(512, 2) fused_kernel(
    const int*   __restrict__ pcls,  const int*   __restrict__ pchg,
    const int*   __restrict__ n_part,
    const float* __restrict__ cl_logits, const float* __restrict__ ch_logits,
    const float* __restrict__ ppos,  const float* __restrict__ fpos,
    const float* __restrict__ pmom,  const float* __restrict__ fmom,
    const float* __restrict__ pe,    const float* __restrict__ fe,
    const float* __restrict__ pred,
    float* __restrict__ out)
{
    __shared__ FusedSmem sm;
    __shared__ unsigned  s_islast;
    __shared__ float     s_fin[8];
    const int t    = threadIdx.x;
    const int lane = t & 31;
    const int w    = t >> 5;

    if (blockIdx.x < Bn) {
        // ================= PAIR-LOSS BLOCK =================
        PairSmem& S = sm.p;
        const int b = blockIdx.x;

        // ---- stage pflow-side tables (one thread per pflow j) ----
        if (t < Nn) {
            const int j  = t;
            const int gj = b * Nn + j;
            float nc[5], nq[3];
            {
                const float* cl = cl_logits + gj * 5;
                float x0 = cl[0], x1 = cl[1], x2 = cl[2], x3 = cl[3], x4 = cl[4];
                float m  = fmaxf(fmaxf(fmaxf(x0, x1), fmaxf(x2, x3)), x4);
                float s  = __expf(x0 - m) + __expf(x1 - m) + __expf(x2 - m)
                         + __expf(x3 - m) + __expf(x4 - m);
                float lse = m + __logf(s);
                nc[0] = lse - x0; nc[1] = lse - x1; nc[2] = lse - x2;
                nc[3] = lse - x3; nc[4] = lse - x4;
            }
            {
                const float* ch = ch_logits + gj * 3;
                float x0 = ch[0], x1 = ch[1], x2 = ch[2];
                float m  = fmaxf(fmaxf(x0, x1), x2);
                float s  = __expf(x0 - m) + __expf(x1 - m) + __expf(x2 - m);
                float lse = m + __logf(s);
                nq[0] = lse - x0; nq[1] = lse - x1; nq[2] = lse - x2;
            }
            float fx = fpos[gj * 3 + 0], fy = fpos[gj * 3 + 1], fz = fpos[gj * 3 + 2];
            float mx = fmom[gj * 3 + 0], my = fmom[gj * 3 + 1], mz = fmom[gj * 3 + 2];
            float fev = fe[gj];
            float np  = fmaf(fx, fx, fmaf(fy, fy, fz * fz));
            float nm  = fmaf(mx, mx, fmaf(my, my, mz * mz));
            float fe2 = fev * fev;
            u64* g = &S.geo[(size_t)j * 10];
            g[0] = dup2(fx); g[1] = dup2(fy); g[2] = dup2(fz); g[3] = dup2(np);
            g[4] = dup2(mx); g[5] = dup2(my); g[6] = dup2(mz); g[7] = dup2(nm);
            g[8] = dup2(fev);
            #pragma unroll
            for (int c = 0; c < 5; c++)
                #pragma unroll
                for (int q = 0; q < 3; q++)
                    S.csum[j * 15 + c * 3 + q] = nc[c] + nq[q] + fe2;
        }

        // ---- per-thread: two particle rows, constants packed f32x2 ----
        const int r   = w & 3;        // row-group: rows [r*64, r*64+64)
        const int q   = w >> 2;       // j-quarter: cols [q*64, q*64+64)
        const int i0  = r * 64 + lane;
        const int i1  = i0 + 32;
        const int gi0 = b * Nn + i0;
        const int gi1 = b * Nn + i1;

        const int cc0 = pcls[gi0] * 3 + pchg[gi0];
        const int cc1 = pcls[gi1] * 3 + pchg[gi1];

        float px0 = ppos[gi0*3+0], py0 = ppos[gi0*3+1], pz0 = ppos[gi0*3+2];
        float qx0 = pmom[gi0*3+0], qy0 = pmom[gi0*3+1], qz0 = pmom[gi0*3+2];
        float pe0v = pe[gi0];
        float px1 = ppos[gi1*3+0], py1 = ppos[gi1*3+1], pz1 = ppos[gi1*3+2];
        float qx1 = pmom[gi1*3+0], qy1 = pmom[gi1*3+1], qz1 = pmom[gi1*3+2];
        float pe1v = pe[gi1];

        const u64 m2x2 = pack2(-2.f*px0, -2.f*px1);
        const u64 m2y2 = pack2(-2.f*py0, -2.f*py1);
        const u64 m2z2 = pack2(-2.f*pz0, -2.f*pz1);
        const u64 n2x2 = pack2(-2.f*qx0, -2.f*qx1);
        const u64 n2y2 = pack2(-2.f*qy0, -2.f*qy1);
        const u64 n2z2 = pack2(-2.f*qz0, -2.f*qz1);
        const u64 m2e2 = pack2(-2.f*pe0v, -2.f*pe1v);
        const u64 rp2  = pack2(fmaf(px0, px0, fmaf(py0, py0, pz0 * pz0)),
                               fmaf(px1, px1, fmaf(py1, py1, pz1 * pz1)));
        const u64 rm2v = pack2(fmaf(qx0, qx0, fmaf(qy0, qy0, qz0 * qz0)),
                               fmaf(qx1, qx1, fmaf(qy1, qy1, qz1 * qz1)));
        const u64 pe2q = pack2(pe0v * pe0v, pe1v * pe1v);

        const float* pc0 = S.csum + cc0;
        const float* pc1 = S.csum + cc1;

        __syncthreads();

        float rm0a = 1e30f, rm0b = 1e30f, rm1a = 1e30f, rm1b = 1e30f;
        const int jbase = q * 64;
        #pragma unroll 8
        for (int jj = 0; jj < 64; jj++) {
            const int j = jbase + jj;
            const u64* g = &S.geo[(size_t)j * 10];
            ulonglong2 Ga = *reinterpret_cast<const ulonglong2*>(g + 0); // fx2, fy2
            ulonglong2 Gb = *reinterpret_cast<const ulonglong2*>(g + 2); // fz2, np2
            ulonglong2 Gc = *reinterpret_cast<const ulonglong2*>(g + 4); // mx2, my2
            ulonglong2 Gd = *reinterpret_cast<const ulonglong2*>(g + 6); // mz2, nm2
            u64 fe2j = g[8];

            u64 d2p = add2(rp2, Gb.y);
            d2p = fma2(m2x2, Ga.x, d2p);
            d2p = fma2(m2y2, Ga.y, d2p);
            d2p = fma2(m2z2, Gb.x, d2p);
            u64 d2m = add2(rm2v, Gd.y);
            d2m = fma2(n2x2, Gc.x, d2m);
            d2m = fma2(n2y2, Gc.y, d2m);
            d2m = fma2(n2z2, Gd.x, d2m);

            u64 csp = pack2(pc0[j * 15], pc1[j * 15]);
            u64 lb  = add2(fma2(m2e2, fe2j, csp), pe2q);

            float dp0, dp1, dm0, dm1, lb0, lb1;
            unpack2(dp0, dp1, d2p);
            unpack2(dm0, dm1, d2m);
            unpack2(lb0, lb1, lb);

            float l0 = lb0 + (fsqrt_ap(dp0) + fsqrt_ap(dm0));
            float l1 = lb1 + (fsqrt_ap(dp1) + fsqrt_ap(dm1));

            if (jj & 1) { rm0b = fminf(rm0b, l0); rm1b = fminf(rm1b, l1); }
            else        { rm0a = fminf(rm0a, l0); rm1a = fminf(rm1a, l1); }

            float cm = warp_min_nonneg(fminf(l0, l1));
            if (lane == 0) S.colmin[r][j] = cm;
        }
        S.rq[q][i0] = fminf(rm0a, rm0b);
        S.rq[q][i1] = fminf(rm1a, rm1b);
        __syncthreads();

        // ---- combine: sum_i rowmin_i + sum_j colmin_j, block reduce ----
        if (t < Nn) {
            float rm = fminf(fminf(S.rq[0][t], S.rq[1][t]),
                             fminf(S.rq[2][t], S.rq[3][t]));
            float cm = fminf(fminf(S.colmin[0][t], S.colmin[1][t]),
                             fminf(S.colmin[2][t], S.colmin[3][t]));
            float v = rm + cm;
            #pragma unroll
            for (int o = 16; o; o >>= 1) v += __shfl_xor_sync(0xffffffffu, v, o);
            if (lane == 0) S.red[w] = v;
        }
        __syncthreads();
        if (t == 0) {
            float s = 0.f;
            #pragma unroll
            for (int wv = 0; wv < 8; wv++) s += S.red[wv];
            g_partials[b] = s;
        }
    } else {
        // ================= SETSIZE BLOCK (R5-proven) =================
        SetSmem& S = sm.s;
        const int b = blockIdx.x - Bn;
        const bool act = t < SMAX;
        const float* base = pred + (size_t)b * Nn * SMAX;

        float a = 0.f;
        if (act) {
            float acc0 = 0.f, acc1 = 0.f, acc2 = 0.f, acc3 = 0.f;
            for (int n = 0; n < Nn; n += 16) {
                float v[16];
                #pragma unroll
                for (int k = 0; k < 16; k++)
                    v[k] = base[(size_t)(n + k) * SMAX + t];
                #pragma unroll
                for (int k = 0; k < 16; k += 4) {
                    acc0 += v[k + 0];
                    acc1 += v[k + 1];
                    acc2 += v[k + 2];
                    acc3 += v[k + 3];
                }
            }
            a = ((acc0 + acc1) + (acc2 + acc3)) * (1.f / Nn);
            S.x[t] = a;
        }

        float v = act ? a : -1e30f;
        #pragma unroll
        for (int o = 16; o; o >>= 1) v = fmaxf(v, __shfl_xor_sync(0xffffffffu, v, o));
        if (lane == 0) S.red[w] = v;
        __syncthreads();
        float m = S.red[0];
        #pragma unroll
        for (int wv = 1; wv < 16; wv++) m = fmaxf(m, S.red[wv]);

        float e = act ? __expf(a - m) : 0.f;
        #pragma unroll
        for (int o = 16; o; o >>= 1) e += __shfl_xor_sync(0xffffffffu, e, o);
        __syncthreads();
        if (lane == 0) S.red[w] = e;
        __syncthreads();

        if (t == 0) {
            float Z = 0.f;
            #pragma unroll
            for (int wv = 0; wv < 16; wv++) Z += S.red[wv];
            float logZ = m + __logf(Z);
            g_partials[Bn + b] = logZ - S.x[n_part[b]];
        }
    }

    // ================= COMPLETION-COUNTER FINAL REDUCTION =================
    if (t == 0) {
        __threadfence();
        unsigned old = atomicAdd(&g_count, 1u);
        s_islast = (old == 2u * Bn - 1u) ? 1u : 0u;
    }
    __syncthreads();
    if (s_islast) {
        if (t < 2 * Bn) {
            float v = ((volatile float*)g_partials)[t];
            #pragma unroll
            for (int o = 16; o; o >>= 1) v += __shfl_xor_sync(0xffffffffu, v, o);
            if (lane == 0) s_fin[w] = v;
        }
        __syncthreads();
        if (t == 0) {
            float s = 0.f;
            #pragma unroll
            for (int wv = 0; wv < 8; wv++) s += s_fin[wv];
            out[0] = s * (1.0f / Bn);
            g_count = 0;   // reset for next graph replay
        }
    }
}

extern "C" void kernel_launch(void* const* d_in, const int* in_sizes, int n_in,
                              void* d_out, int out_size)
{
    const int*   pcls  = (const int*)  d_in[0];
    const int*   pchg  = (const int*)  d_in[1];
    const int*   npart = (const int*)  d_in[2];
    const float* cl    = (const float*)d_in[3];
    const float* ch    = (const float*)d_in[4];
    const float* ppos  = (const float*)d_in[5];
    const float* fpos  = (const float*)d_in[6];
    const float* pmom  = (const float*)d_in[7];
    const float* fmom  = (const float*)d_in[8];
    const float* pe    = (const float*)d_in[9];
    const float* fe    = (const float*)d_in[10];
    const float* pred  = (const float*)d_in[11];

    fused_kernel<<<2 * Bn, 512>>>(pcls, pchg, npart, cl, ch,
                                  ppos, fpos, pmom, fmom, pe, fe, pred,
                                  (float*)d_out);
}

// round 9
// speedup vs baseline: 1.1366x; 1.0019x over previous
#include <cuda_runtime.h>

static constexpr int Bn   = 128;
static constexpr int Nn   = 256;
static constexpr int SMAX = 300;

typedef unsigned long long u64;

__device__ float    g_partials[2 * Bn];  // [0..Bn) pair, [Bn..2Bn) setsize
__device__ unsigned g_count = 0;

__device__ __forceinline__ float fsqrt_ap(float x) {
    float r;
    asm("sqrt.approx.f32 %0, %1;" : "=f"(r) : "f"(x));
    return r;
}
// Warp-wide min for non-negative floats (u32 ordering == float ordering;
// NaN bit patterns are huge, so they lose the min — desired).
__device__ __forceinline__ float warp_min_nonneg(float x) {
    unsigned u = __float_as_uint(x), r;
    asm("redux.sync.min.u32 %0, %1, 0xffffffff;" : "=r"(r) : "r"(u));
    return __uint_as_float(r);
}
// ---- f32x2 packed helpers (Blackwell) ----
__device__ __forceinline__ u64 pack2(float lo, float hi) {
    u64 d;
    asm("mov.b64 %0, {%1, %2};" : "=l"(d) : "f"(lo), "f"(hi));
    return d;
}
__device__ __forceinline__ void unpack2(float& lo, float& hi, u64 v) {
    asm("mov.b64 {%0, %1}, %2;" : "=f"(lo), "=f"(hi) : "l"(v));
}
__device__ __forceinline__ u64 dup2(float x) { return pack2(x, x); }
__device__ __forceinline__ u64 fma2(u64 a, u64 b, u64 c) {
    u64 d;
    asm("fma.rn.f32x2 %0, %1, %2, %3;" : "=l"(d) : "l"(a), "l"(b), "l"(c));
    return d;
}
__device__ __forceinline__ u64 add2(u64 a, u64 b) {
    u64 d;
    asm("add.rn.f32x2 %0, %1, %2;" : "=l"(d) : "l"(a), "l"(b));
    return d;
}

struct PairSmem {
    u64   geo[Nn * 10];     // per j (80B): fx2,fy2,fz2,np2, mx2,my2,mz2,nm2, fe2, pad
    float csum[Nn * 15];    // nllc[c]+nllq[q]+fe^2 per (j, cls*3+chg)
    float colmin[4][Nn];    // per row-group column mins
    float rq[4][Nn];        // per j-quarter row mins
    float red[16];
};
struct SetSmem { float x[SMAX]; float red[16]; };
union FusedSmem { PairSmem p; SetSmem s; };

// ---------------------------------------------------------------------------
// grid = 256 x 512 threads. blocks [0,128): pair loss; [128,256): setsize.
// Pair inner loop is software-pipelined: iteration j+1's SMEM loads are issued
// before iteration j's arithmetic, hiding the 29-cyc LDS latency at 4 warps/
// SMSP. Setsize streams with 32 loads in flight. Last block reduces partials.
// ---------------------------------------------------------------------------
__global__ void __launch_bounds__(512, 2) fused_kernel(
    const int*   __restrict__ pcls,  const int*   __restrict__ pchg,
    const int*   __restrict__ n_part,
    const float* __restrict__ cl_logits, const float* __restrict__ ch_logits,
    const float* __restrict__ ppos,  const float* __restrict__ fpos,
    const float* __restrict__ pmom,  const float* __restrict__ fmom,
    const float* __restrict__ pe,    const float* __restrict__ fe,
    const float* __restrict__ pred,
    float* __restrict__ out)
{
    __shared__ FusedSmem sm;
    __shared__ unsigned  s_islast;
    __shared__ float     s_fin[8];
    const int t    = threadIdx.x;
    const int lane = t & 31;
    const int w    = t >> 5;

    if (blockIdx.x < Bn) {
        // ================= PAIR-LOSS BLOCK =================
        PairSmem& S = sm.p;
        const int b = blockIdx.x;

        // ---- stage pflow-side tables (one thread per pflow j) ----
        if (t < Nn) {
            const int j  = t;
            const int gj = b * Nn + j;
            float nc[5], nq[3];
            {
                const float* cl = cl_logits + gj * 5;
                float x0 = cl[0], x1 = cl[1], x2 = cl[2], x3 = cl[3], x4 = cl[4];
                float m  = fmaxf(fmaxf(fmaxf(x0, x1), fmaxf(x2, x3)), x4);
                float s  = __expf(x0 - m) + __expf(x1 - m) + __expf(x2 - m)
                         + __expf(x3 - m) + __expf(x4 - m);
                float lse = m + __logf(s);
                nc[0] = lse - x0; nc[1] = lse - x1; nc[2] = lse - x2;
                nc[3] = lse - x3; nc[4] = lse - x4;
            }
            {
                const float* ch = ch_logits + gj * 3;
                float x0 = ch[0], x1 = ch[1], x2 = ch[2];
                float m  = fmaxf(fmaxf(x0, x1), x2);
                float s  = __expf(x0 - m) + __expf(x1 - m) + __expf(x2 - m);
                float lse = m + __logf(s);
                nq[0] = lse - x0; nq[1] = lse - x1; nq[2] = lse - x2;
            }
            float fx = fpos[gj * 3 + 0], fy = fpos[gj * 3 + 1], fz = fpos[gj * 3 + 2];
            float mx = fmom[gj * 3 + 0], my = fmom[gj * 3 + 1], mz = fmom[gj * 3 + 2];
            float fev = fe[gj];
            float np  = fmaf(fx, fx, fmaf(fy, fy, fz * fz));
            float nm  = fmaf(mx, mx, fmaf(my, my, mz * mz));
            float fe2 = fev * fev;
            u64* g = &S.geo[(size_t)j * 10];
            g[0] = dup2(fx); g[1] = dup2(fy); g[2] = dup2(fz); g[3] = dup2(np);
            g[4] = dup2(mx); g[5] = dup2(my); g[6] = dup2(mz); g[7] = dup2(nm);
            g[8] = dup2(fev);
            #pragma unroll
            for (int c = 0; c < 5; c++)
                #pragma unroll
                for (int q = 0; q < 3; q++)
                    S.csum[j * 15 + c * 3 + q] = nc[c] + nq[q] + fe2;
        }

        // ---- per-thread: two particle rows, constants packed f32x2 ----
        const int r   = w & 3;        // row-group: rows [r*64, r*64+64)
        const int q   = w >> 2;       // j-quarter: cols [q*64, q*64+64)
        const int i0  = r * 64 + lane;
        const int i1  = i0 + 32;
        const int gi0 = b * Nn + i0;
        const int gi1 = b * Nn + i1;

        const int cc0 = pcls[gi0] * 3 + pchg[gi0];
        const int cc1 = pcls[gi1] * 3 + pchg[gi1];

        float px0 = ppos[gi0*3+0], py0 = ppos[gi0*3+1], pz0 = ppos[gi0*3+2];
        float qx0 = pmom[gi0*3+0], qy0 = pmom[gi0*3+1], qz0 = pmom[gi0*3+2];
        float pe0v = pe[gi0];
        float px1 = ppos[gi1*3+0], py1 = ppos[gi1*3+1], pz1 = ppos[gi1*3+2];
        float qx1 = pmom[gi1*3+0], qy1 = pmom[gi1*3+1], qz1 = pmom[gi1*3+2];
        float pe1v = pe[gi1];

        const u64 m2x2 = pack2(-2.f*px0, -2.f*px1);
        const u64 m2y2 = pack2(-2.f*py0, -2.f*py1);
        const u64 m2z2 = pack2(-2.f*pz0, -2.f*pz1);
        const u64 n2x2 = pack2(-2.f*qx0, -2.f*qx1);
        const u64 n2y2 = pack2(-2.f*qy0, -2.f*qy1);
        const u64 n2z2 = pack2(-2.f*qz0, -2.f*qz1);
        const u64 m2e2 = pack2(-2.f*pe0v, -2.f*pe1v);
        // fold pe^2 into the row constants once
        const u64 rp2  = pack2(fmaf(px0, px0, fmaf(py0, py0, pz0 * pz0)),
                               fmaf(px1, px1, fmaf(py1, py1, pz1 * pz1)));
        const u64 rm2v = pack2(fmaf(qx0, qx0, fmaf(qy0, qy0, qz0 * qz0)),
                               fmaf(qx1, qx1, fmaf(qy1, qy1, qz1 * qz1)));
        const u64 pe2q = pack2(pe0v * pe0v, pe1v * pe1v);

        const float* pc0 = S.csum + cc0;
        const float* pc1 = S.csum + cc1;
        const int jbase = q * 64;

        __syncthreads();

        // ---- software-pipelined main loop ----
        float rm0a = 1e30f, rm1a = 1e30f;

        // prologue: load iteration 0
        const u64* g0 = &S.geo[(size_t)jbase * 10];
        ulonglong2 Ga = *reinterpret_cast<const ulonglong2*>(g0 + 0);
        ulonglong2 Gb = *reinterpret_cast<const ulonglong2*>(g0 + 2);
        ulonglong2 Gc = *reinterpret_cast<const ulonglong2*>(g0 + 4);
        ulonglong2 Gd = *reinterpret_cast<const ulonglong2*>(g0 + 6);
        u64   fe2j = g0[8];
        float cs0  = pc0[jbase * 15];
        float cs1  = pc1[jbase * 15];

        #pragma unroll 4
        for (int jj = 0; jj < 64; jj++) {
            const int j = jbase + jj;
            // consume current-iteration buffers
            ulonglong2 a0 = Ga, b0 = Gb, c0 = Gc, d0 = Gd;
            u64   fej = fe2j;
            float s0 = cs0, s1 = cs1;

            // prefetch next iteration (use-distance = full body)
            if (jj < 63) {
                const u64* gn = &S.geo[(size_t)(j + 1) * 10];
                Ga = *reinterpret_cast<const ulonglong2*>(gn + 0);
                Gb = *reinterpret_cast<const ulonglong2*>(gn + 2);
                Gc = *reinterpret_cast<const ulonglong2*>(gn + 4);
                Gd = *reinterpret_cast<const ulonglong2*>(gn + 6);
                fe2j = gn[8];
                cs0  = pc0[(j + 1) * 15];
                cs1  = pc1[(j + 1) * 15];
            }

            u64 d2p = add2(rp2, b0.y);
            d2p = fma2(m2x2, a0.x, d2p);
            d2p = fma2(m2y2, a0.y, d2p);
            d2p = fma2(m2z2, b0.x, d2p);
            u64 d2m = add2(rm2v, d0.y);
            d2m = fma2(n2x2, c0.x, d2m);
            d2m = fma2(n2y2, c0.y, d2m);
            d2m = fma2(n2z2, d0.x, d2m);

            u64 csp = pack2(s0, s1);
            u64 lb  = add2(fma2(m2e2, fej, csp), pe2q);

            float dp0, dp1, dm0, dm1, lb0, lb1;
            unpack2(dp0, dp1, d2p);
            unpack2(dm0, dm1, d2m);
            unpack2(lb0, lb1, lb);

            float l0 = lb0 + (fsqrt_ap(dp0) + fsqrt_ap(dm0));
            float l1 = lb1 + (fsqrt_ap(dp1) + fsqrt_ap(dm1));

            rm0a = fminf(rm0a, l0);
            rm1a = fminf(rm1a, l1);

            float cm = warp_min_nonneg(fminf(l0, l1));
            if (lane == 0) S.colmin[r][j] = cm;
        }
        S.rq[q][i0] = rm0a;
        S.rq[q][i1] = rm1a;
        __syncthreads();

        // ---- combine: sum_i rowmin_i + sum_j colmin_j, block reduce ----
        if (t < Nn) {
            float rm = fminf(fminf(S.rq[0][t], S.rq[1][t]),
                             fminf(S.rq[2][t], S.rq[3][t]));
            float cm = fminf(fminf(S.colmin[0][t], S.colmin[1][t]),
                             fminf(S.colmin[2][t], S.colmin[3][t]));
            float v = rm + cm;
            #pragma unroll
            for (int o = 16; o; o >>= 1) v += __shfl_xor_sync(0xffffffffu, v, o);
            if (lane == 0) S.red[w] = v;
        }
        __syncthreads();
        if (t == 0) {
            float s = 0.f;
            #pragma unroll
            for (int wv = 0; wv < 8; wv++) s += S.red[wv];
            g_partials[b] = s;
        }
    } else {
        // ================= SETSIZE BLOCK (32-deep MLP) =================
        SetSmem& S = sm.s;
        const int b = blockIdx.x - Bn;
        const bool act = t < SMAX;
        const float* base = pred + (size_t)b * Nn * SMAX;

        float a = 0.f;
        if (act) {
            float acc0 = 0.f, acc1 = 0.f, acc2 = 0.f, acc3 = 0.f;
            for (int n = 0; n < Nn; n += 32) {
                float v[32];
                #pragma unroll
                for (int k = 0; k < 32; k++)
                    v[k] = base[(size_t)(n + k) * SMAX + t];
                #pragma unroll
                for (int k = 0; k < 32; k += 4) {
                    acc0 += v[k + 0];
                    acc1 += v[k + 1];
                    acc2 += v[k + 2];
                    acc3 += v[k + 3];
                }
            }
            a = ((acc0 + acc1) + (acc2 + acc3)) * (1.f / Nn);
            S.x[t] = a;
        }

        float v = act ? a : -1e30f;
        #pragma unroll
        for (int o = 16; o; o >>= 1) v = fmaxf(v, __shfl_xor_sync(0xffffffffu, v, o));
        if (lane == 0) S.red[w] = v;
        __syncthreads();
        float m = S.red[0];
        #pragma unroll
        for (int wv = 1; wv < 16; wv++) m = fmaxf(m, S.red[wv]);

        float e = act ? __expf(a - m) : 0.f;
        #pragma unroll
        for (int o = 16; o; o >>= 1) e += __shfl_xor_sync(0xffffffffu, e, o);
        __syncthreads();
        if (lane == 0) S.red[w] = e;
        __syncthreads();

        if (t == 0) {
            float Z = 0.f;
            #pragma unroll
            for (int wv = 0; wv < 16; wv++) Z += S.red[wv];
            float logZ = m + __logf(Z);
            g_partials[Bn + b] = logZ - S.x[n_part[b]];
        }
    }

    // ================= COMPLETION-COUNTER FINAL REDUCTION =================
    if (t == 0) {
        __threadfence();
        unsigned old = atomicAdd(&g_count, 1u);
        s_islast = (old == 2u * Bn - 1u) ? 1u : 0u;
    }
    __syncthreads();
    if (s_islast) {
        if (t < 2 * Bn) {
            float v = ((volatile float*)g_partials)[t];
            #pragma unroll
            for (int o = 16; o; o >>= 1) v += __shfl_xor_sync(0xffffffffu, v, o);
            if (lane == 0) s_fin[w] = v;
        }
        __syncthreads();
        if (t == 0) {
            float s = 0.f;
            #pragma unroll
            for (int wv = 0; wv < 8; wv++) s += s_fin[wv];
            out[0] = s * (1.0f / Bn);
            g_count = 0;   // reset for next graph replay
        }
    }
}

extern "C" void kernel_launch(void* const* d_in, const int* in_sizes, int n_in,
                              void* d_out, int out_size)
{
    const int*   pcls  = (const int*)  d_in[0];
    const int*   pchg  = (const int*)  d_in[1];
    const int*   npart = (const int*)  d_in[2];
    const float* cl    = (const float*)d_in[3];
    const float* ch    = (const float*)d_in[4];
    const float* ppos  = (const float*)d_in[5];
    const float* fpos  = (const float*)d_in[6];
    const float* pmom  = (const float*)d_in[7];
    const float* fmom  = (const float*)d_in[8];
    const float* pe    = (const float*)d_in[9];
    const float* fe    = (const float*)d_in[10];
    const float* pred  = (const float*)d_in[11];

    fused_kernel<<<2 * Bn, 512>>>(pcls, pchg, npart, cl, ch,
                                  ppos, fpos, pmom, fmom, pe, fe, pred,
                                  (float*)d_out);
}